// round 7
// baseline (speedup 1.0000x reference)
#include <cuda_runtime.h>
#include <cuda_bf16.h>

// Problem constants
#define N_NODES   4000
#define NNODES    4001          // depot + nodes
#define EMBED     128
#define NC        25            // grid cells per dim (cell width = 0.04)
#define NCELLS    (NC * NC)     // 625
#define THRESH    0.04f
#define MAXS      384           // cap on 2-hop set size (expected ~80, max ~130)

// ---------------- device scratch (no allocations allowed) ----------------
__device__ float g_loc_x[NNODES];
__device__ float g_loc_y[NNODES];
__device__ float g_td[NNODES];
__device__ int   g_cell_count[NCELLS];
__device__ int   g_cell_start[NCELLS];
__device__ int   g_cell_cursor[NCELLS];
__device__ int   g_cell_nodes[NNODES];
__device__ int   g_node_cell[NNODES];
__device__ float g_fv1[NNODES * EMBED];

// ---------------- helpers ----------------
__device__ __forceinline__ int cell1d(float x) {
    int c = (int)(x * 25.0f);
    return min(NC - 1, max(0, c));
}

// Match reference: sqrt(dx*dx + dy*dy) <= 0.04f, no FMA contraction, IEEE sqrt.
__device__ __forceinline__ bool adj(float ax, float ay, float bx, float by) {
    float dx = __fadd_rn(ax, -bx);
    float dy = __fadd_rn(ay, -by);
    float d2 = __fadd_rn(__fmul_rn(dx, dx), __fmul_rn(dy, dy));
    return __fsqrt_rn(d2) <= THRESH;
}

// ---------------- setup: build unified node arrays, zero counts ----------------
__global__ void k_setup(const float* __restrict__ node_loc,
                        const float* __restrict__ td,
                        const float* __restrict__ depot) {
    int i = blockIdx.x * blockDim.x + threadIdx.x;
    if (i < NCELLS) g_cell_count[i] = 0;
    if (i < NNODES) {
        if (i == 0) {
            g_loc_x[0] = depot[0];
            g_loc_y[0] = depot[1];
            g_td[0]    = 0.0f;
        } else {
            g_loc_x[i] = node_loc[(i - 1) * 2 + 0];
            g_loc_y[i] = node_loc[(i - 1) * 2 + 1];
            g_td[i]    = td[i - 1];
        }
    }
}

// ---------------- grid build ----------------
__global__ void k_count() {
    int i = blockIdx.x * blockDim.x + threadIdx.x;
    if (i >= NNODES) return;
    int c = cell1d(g_loc_y[i]) * NC + cell1d(g_loc_x[i]);
    g_node_cell[i] = c;
    atomicAdd(&g_cell_count[c], 1);
}

__global__ void k_scan() {   // 1 block, 1024 threads; Hillis–Steele over 625 cells
    __shared__ int s[1024];
    int t = threadIdx.x;
    s[t] = (t < NCELLS) ? g_cell_count[t] : 0;
    __syncthreads();
    for (int off = 1; off < 1024; off <<= 1) {
        int v = (t >= off) ? s[t - off] : 0;
        __syncthreads();
        s[t] += v;
        __syncthreads();
    }
    if (t < NCELLS) {
        int st = s[t] - g_cell_count[t];   // exclusive prefix
        g_cell_start[t]  = st;
        g_cell_cursor[t] = st;
    }
}

__global__ void k_scatter() {
    int i = blockIdx.x * blockDim.x + threadIdx.x;
    if (i >= NNODES) return;
    int pos = atomicAdd(&g_cell_cursor[g_node_cell[i]], 1);
    g_cell_nodes[pos] = i;
}

// Deterministic ordering: sort each cell's segment ascending (avg ~6 elems).
__global__ void k_sortcells() {
    int c = blockIdx.x * blockDim.x + threadIdx.x;
    if (c >= NCELLS) return;
    int s = g_cell_start[c], n = g_cell_count[c];
    for (int i = 1; i < n; i++) {
        int key = g_cell_nodes[s + i];
        int j = i - 1;
        while (j >= 0 && g_cell_nodes[s + j] > key) {
            g_cell_nodes[s + j + 1] = g_cell_nodes[s + j];
            j--;
        }
        g_cell_nodes[s + j + 1] = key;
    }
}

// ---------------- fv_1[v] = sum_{w in N(v)} relu(W0 * feat_w + b) ----------------
// One block per vertex, thread d owns output dim d (W row in registers).
__global__ void __launch_bounds__(EMBED) k_fv1(const float* __restrict__ W,
                                               const float* __restrict__ b) {
    int v = blockIdx.x;
    int d = threadIdx.x;
    float w0 = W[d * 3 + 0], w1 = W[d * 3 + 1], w2 = W[d * 3 + 2];
    float bb = b[d];
    float vx = g_loc_x[v], vy = g_loc_y[v];
    int cx = cell1d(vx), cy = cell1d(vy);
    float acc = 0.0f;
    for (int oy = -1; oy <= 1; oy++) {
        int yy = cy + oy;
        if (yy < 0 || yy >= NC) continue;
        for (int ox = -1; ox <= 1; ox++) {
            int xx = cx + ox;
            if (xx < 0 || xx >= NC) continue;
            int c = yy * NC + xx;
            int s = g_cell_start[c], e = s + g_cell_count[c];
            for (int i = s; i < e; i++) {
                int u = g_cell_nodes[i];            // broadcast loads
                float ux = g_loc_x[u], uy = g_loc_y[u];
                if (adj(vx, vy, ux, uy)) {
                    float f = fmaf(w2, g_td[u], fmaf(w1, uy, fmaf(w0, ux, bb)));
                    acc += fmaxf(f, 0.0f);
                }
            }
        }
    }
    g_fv1[v * EMBED + d] = acc;
}

// ---------------- fv_2[v] = sum_{u in S(v)} c_u * fv_1[u] ----------------
// S(v) = union of N(w), w in N(v)   (== 2-hop reachable set, incl. v)
// c_u  = |{w in S(v) : d(u,w) <= tau}|
__global__ void __launch_bounds__(EMBED) k_fv2(float* __restrict__ out) {
    int v    = blockIdx.x;
    int tid  = threadIdx.x;
    int lane = tid & 31;
    int warp = tid >> 5;

    __shared__ float s_nx[128], s_ny[128];
    __shared__ int   s_nn;
    __shared__ int   s_sidx[MAXS];
    __shared__ float s_sx[MAXS], s_sy[MAXS];
    __shared__ int   s_ns;
    __shared__ float s_c[MAXS];

    float vx = g_loc_x[v], vy = g_loc_y[v];
    int cx = cell1d(vx), cy = cell1d(vy);

    // --- Phase A: 1-hop neighbor positions (warp 0, deterministic ballot-append) ---
    if (warp == 0) {
        int nn = 0;
        for (int oy = -1; oy <= 1; oy++) {
            int yy = cy + oy;
            if (yy < 0 || yy >= NC) continue;
            for (int ox = -1; ox <= 1; ox++) {
                int xx = cx + ox;
                if (xx < 0 || xx >= NC) continue;
                int c = yy * NC + xx;
                int s = g_cell_start[c], e = s + g_cell_count[c];
                for (int base = s; base < e; base += 32) {
                    int i = base + lane;
                    bool val = false;
                    float ux = 0.0f, uy = 0.0f;
                    if (i < e) {
                        int u = g_cell_nodes[i];
                        ux = g_loc_x[u];
                        uy = g_loc_y[u];
                        val = adj(vx, vy, ux, uy);
                    }
                    unsigned m = __ballot_sync(0xffffffffu, val);
                    int pos = nn + __popc(m & ((1u << lane) - 1u));
                    if (val && pos < 128) { s_nx[pos] = ux; s_ny[pos] = uy; }
                    nn += __popc(m);
                }
            }
        }
        if (lane == 0) s_nn = min(nn, 128);
    }
    __syncthreads();
    int nn = s_nn;

    // --- Phase B: build S (warp 0; candidates within 5x5 cells cover dist <= 0.08) ---
    if (warp == 0) {
        int ns = 0;
        for (int oy = -2; oy <= 2; oy++) {
            int yy = cy + oy;
            if (yy < 0 || yy >= NC) continue;
            for (int ox = -2; ox <= 2; ox++) {
                int xx = cx + ox;
                if (xx < 0 || xx >= NC) continue;
                int c = yy * NC + xx;
                int s = g_cell_start[c], e = s + g_cell_count[c];
                for (int base = s; base < e; base += 32) {
                    int i = base + lane;
                    bool val = false;
                    int  u  = 0;
                    float ux = 0.0f, uy = 0.0f;
                    if (i < e) {
                        u  = g_cell_nodes[i];
                        ux = g_loc_x[u];
                        uy = g_loc_y[u];
                        for (int k = 0; k < nn; k++) {
                            if (adj(ux, uy, s_nx[k], s_ny[k])) { val = true; break; }
                        }
                    }
                    unsigned m = __ballot_sync(0xffffffffu, val);
                    int pos = ns + __popc(m & ((1u << lane) - 1u));
                    if (val && pos < MAXS) {
                        s_sidx[pos] = u;
                        s_sx[pos]   = ux;
                        s_sy[pos]   = uy;
                    }
                    ns += __popc(m);
                }
            }
        }
        if (lane == 0) s_ns = min(ns, MAXS);
    }
    __syncthreads();
    int ns = s_ns;

    // --- Phase C: c_u = |S ∩ N(u)| (exact integer counts, order-independent) ---
    for (int j = tid; j < ns; j += EMBED) {
        float ux = s_sx[j], uy = s_sy[j];
        int cnt = 0;
        for (int k = 0; k < ns; k++)
            cnt += adj(ux, uy, s_sx[k], s_sy[k]) ? 1 : 0;
        s_c[j] = (float)cnt;
    }
    __syncthreads();

    // --- Phase D: weighted gather of fv_1 rows (coalesced 512B rows, L2-resident) ---
    float acc = 0.0f;
#pragma unroll 4
    for (int j = 0; j < ns; j++) {
        acc += s_c[j] * g_fv1[s_sidx[j] * EMBED + tid];
    }
    out[v * EMBED + tid] = acc;
}

// ---------------- launch ----------------
extern "C" void kernel_launch(void* const* d_in, const int* in_sizes, int n_in,
                              void* d_out, int out_size) {
    const float* node_loc = (const float*)d_in[0];   // [4000, 2]
    const float* td       = (const float*)d_in[1];   // [4000, 1]
    const float* depot    = (const float*)d_in[2];   // [1, 2]
    const float* W0_w     = (const float*)d_in[3];   // [128, 3]
    const float* W0_b     = (const float*)d_in[4];   // [128]
    float* out = (float*)d_out;                      // [4001, 128]

    const int T = 256;
    const int BN = (NNODES + T - 1) / T;

    k_setup<<<BN, T>>>(node_loc, td, depot);
    k_count<<<BN, T>>>();
    k_scan<<<1, 1024>>>();
    k_scatter<<<BN, T>>>();
    k_sortcells<<<(NCELLS + 127) / 128, 128>>>();
    k_fv1<<<NNODES, EMBED>>>(W0_w, W0_b);
    k_fv2<<<NNODES, EMBED>>>(out);
}

// round 8
// speedup vs baseline: 2.8292x; 2.8292x over previous
#include <cuda_runtime.h>
#include <cuda_bf16.h>

// Problem constants
#define N_NODES   4000
#define NNODES    4001          // depot + nodes
#define EMBED     128
#define NC        25            // grid cells per dim (cell width = 0.04)
#define NCELLS    (NC * NC)     // 625
#define THRESH    0.04f
#define MAXS      384           // cap on 2-hop set size (expected ~80, max ~140)
#define MAXDEG    96            // cap on 1-hop degree (expected ~21, max ~50)
#define BMWORDS   128           // ceil(4001/32) = 126, padded

// ---------------- device scratch (no allocations allowed) ----------------
__device__ float g_loc_x[NNODES];
__device__ float g_loc_y[NNODES];
__device__ float g_td[NNODES];
__device__ int   g_cell_start[NCELLS];
__device__ int   g_cell_count[NCELLS];
__device__ int   g_cell_nodes[NNODES];
__device__ int   g_node_cell[NNODES];
__device__ int   g_deg[NNODES];
__device__ int   g_nbr[NNODES * MAXDEG];
__device__ float g_fv1[NNODES * EMBED];

// ---------------- helpers ----------------
__device__ __forceinline__ int cell1d(float x) {
    int c = (int)(x * 25.0f);
    return min(NC - 1, max(0, c));
}

// Match reference: sqrt(dx*dx + dy*dy) <= 0.04f, no FMA contraction, IEEE sqrt.
__device__ __forceinline__ bool adj(float ax, float ay, float bx, float by) {
    float dx = __fadd_rn(ax, -bx);
    float dy = __fadd_rn(ay, -by);
    float d2 = __fadd_rn(__fmul_rn(dx, dx), __fmul_rn(dy, dy));
    return __fsqrt_rn(d2) <= THRESH;
}

// ---------------- fused grid build: single block, 1024 threads ----------------
// setup -> per-cell count (smem atomics) -> scan -> scatter -> per-cell sort
__global__ void __launch_bounds__(1024) k_grid(const float* __restrict__ node_loc,
                                               const float* __restrict__ td,
                                               const float* __restrict__ depot) {
    __shared__ int s_cnt[1024];
    __shared__ int s_start[NCELLS];
    __shared__ int s_cur[NCELLS];
    int t = threadIdx.x;

    if (t < 1024) s_cnt[t] = 0;
    __syncthreads();

    // setup + count
    for (int i = t; i < NNODES; i += 1024) {
        float x, y, d;
        if (i == 0) { x = depot[0]; y = depot[1]; d = 0.0f; }
        else        { x = node_loc[(i - 1) * 2 + 0]; y = node_loc[(i - 1) * 2 + 1]; d = td[i - 1]; }
        g_loc_x[i] = x; g_loc_y[i] = y; g_td[i] = d;
        int c = cell1d(y) * NC + cell1d(x);
        g_node_cell[i] = c;
        atomicAdd(&s_cnt[c], 1);
    }
    __syncthreads();

    // inclusive scan (Hillis-Steele) over 625 cells, then exclusive start
    int cnt = (t < NCELLS) ? s_cnt[t] : 0;
    __shared__ int s_scan[1024];
    s_scan[t] = cnt;
    __syncthreads();
    for (int off = 1; off < 1024; off <<= 1) {
        int v = (t >= off) ? s_scan[t - off] : 0;
        __syncthreads();
        s_scan[t] += v;
        __syncthreads();
    }
    if (t < NCELLS) {
        int st = s_scan[t] - cnt;
        s_start[t] = st;
        s_cur[t]   = st;
        g_cell_start[t] = st;
        g_cell_count[t] = cnt;
    }
    __syncthreads();

    // scatter
    for (int i = t; i < NNODES; i += 1024) {
        int pos = atomicAdd(&s_cur[g_node_cell[i]], 1);
        g_cell_nodes[pos] = i;
    }
    __syncthreads();

    // deterministic order: insertion-sort each cell segment (avg ~6.4 elems)
    for (int c = t; c < NCELLS; c += 1024) {
        int s = s_start[c], n = (c < NCELLS) ? (s_scan[c] - s_start[c]) : 0;
        for (int i = 1; i < n; i++) {
            int key = g_cell_nodes[s + i];
            int j = i - 1;
            while (j >= 0 && g_cell_nodes[s + j] > key) {
                g_cell_nodes[s + j + 1] = g_cell_nodes[s + j];
                j--;
            }
            g_cell_nodes[s + j + 1] = key;
        }
    }
}

// ---------------- adjacency CSR (fixed stride): one warp per vertex ----------------
// Candidates in 3x3 cells == 3 contiguous row-segments of g_cell_nodes.
__global__ void __launch_bounds__(256) k_adj() {
    int warp_g = (blockIdx.x * blockDim.x + threadIdx.x) >> 5;
    int lane   = threadIdx.x & 31;
    if (warp_g >= NNODES) return;
    int v = warp_g;

    float vx = g_loc_x[v], vy = g_loc_y[v];
    int cx = cell1d(vx), cy = cell1d(vy);
    int x0 = max(0, cx - 1), x1 = min(NC - 1, cx + 1);
    int y0 = max(0, cy - 1), y1 = min(NC - 1, cy + 1);

    int deg = 0;
    for (int yy = y0; yy <= y1; yy++) {
        int c0 = yy * NC + x0, c1 = yy * NC + x1;
        int s = g_cell_start[c0];
        int e = g_cell_start[c1] + g_cell_count[c1];
        for (int base = s; base < e; base += 32) {
            int i = base + lane;
            bool val = false;
            int u = 0;
            if (i < e) {
                u = g_cell_nodes[i];
                val = adj(vx, vy, g_loc_x[u], g_loc_y[u]);
            }
            unsigned m = __ballot_sync(0xffffffffu, val);
            int pos = deg + __popc(m & ((1u << lane) - 1u));
            if (val && pos < MAXDEG) g_nbr[v * MAXDEG + pos] = u;
            deg += __popc(m);
        }
    }
    if (lane == 0) g_deg[v] = min(deg, MAXDEG);
}

// ---------------- fv_1[v] = sum_{w in N(v)} relu(W0 * feat_w + b) ----------------
__global__ void __launch_bounds__(EMBED) k_fv1(const float* __restrict__ W,
                                               const float* __restrict__ b) {
    int v = blockIdx.x;
    int d = threadIdx.x;
    float w0 = W[d * 3 + 0], w1 = W[d * 3 + 1], w2 = W[d * 3 + 2];
    float bb = b[d];
    int deg = g_deg[v];
    const int* nbr = &g_nbr[v * MAXDEG];
    float acc = 0.0f;
    for (int i = 0; i < deg; i++) {
        int u = nbr[i];                              // broadcast
        float f = fmaf(w2, g_td[u], fmaf(w1, g_loc_y[u], fmaf(w0, g_loc_x[u], bb)));
        acc += fmaxf(f, 0.0f);
    }
    g_fv1[v * EMBED + d] = acc;
}

// ---------------- fv_2[v] = sum_{u in S(v)} c_u * fv_1[u] ----------------
// S(v) = union_{w in N(v)} N(w)  (marked in a 4001-bit shared bitmap)
// c_u  = |N(u) ∩ S(v)|           (exact ints -> fp32-exact)
__global__ void __launch_bounds__(EMBED) k_fv2(float* __restrict__ out) {
    int v    = blockIdx.x;
    int tid  = threadIdx.x;
    int lane = tid & 31;
    int warp = tid >> 5;

    __shared__ int      s_nbr[MAXDEG];
    __shared__ unsigned s_bm[BMWORDS];
    __shared__ int      s_sidx[MAXS];
    __shared__ float    s_c[MAXS];
    __shared__ int      s_ns;

    int deg = g_deg[v];

    // load N(v) list; zero bitmap
    if (tid < MAXDEG && tid < deg) s_nbr[tid] = g_nbr[v * MAXDEG + tid];
    if (tid < BMWORDS) s_bm[tid] = 0u;
    __syncthreads();

    // --- mark S: all 4 warps, one w per warp-iteration; lanes stream N(w) ---
    for (int i = warp; i < deg; i += 4) {
        int w  = s_nbr[i];
        int dw = g_deg[w];
        const int* nw = &g_nbr[w * MAXDEG];
        for (int k = lane; k < dw; k += 32) {
            int u = nw[k];
            atomicOr(&s_bm[u >> 5], 1u << (u & 31));
        }
    }
    __syncthreads();

    // --- compact S deterministically (warp 0): 5x5 cells = 5 contiguous segments ---
    if (warp == 0) {
        float vx = g_loc_x[v], vy = g_loc_y[v];
        int cx = cell1d(vx), cy = cell1d(vy);
        int x0 = max(0, cx - 2), x1 = min(NC - 1, cx + 2);
        int y0 = max(0, cy - 2), y1 = min(NC - 1, cy + 2);
        int ns = 0;
        for (int yy = y0; yy <= y1; yy++) {
            int c0 = yy * NC + x0, c1 = yy * NC + x1;
            int s = g_cell_start[c0];
            int e = g_cell_start[c1] + g_cell_count[c1];
            for (int base = s; base < e; base += 32) {
                int i = base + lane;
                bool val = false;
                int u = 0;
                if (i < e) {
                    u = g_cell_nodes[i];
                    val = (s_bm[u >> 5] >> (u & 31)) & 1u;
                }
                unsigned m = __ballot_sync(0xffffffffu, val);
                int pos = ns + __popc(m & ((1u << lane) - 1u));
                if (val && pos < MAXS) s_sidx[pos] = u;
                ns += __popc(m);
            }
        }
        if (lane == 0) s_ns = min(ns, MAXS);
    }
    __syncthreads();
    int ns = s_ns;

    // --- c_u = |N(u) ∩ S| via bitmap tests (~deg_u per u) ---
    for (int j = tid; j < ns; j += EMBED) {
        int u  = s_sidx[j];
        int du = g_deg[u];
        const int* nu = &g_nbr[u * MAXDEG];
        int cnt = 0;
        for (int k = 0; k < du; k++) {
            int w = nu[k];
            cnt += (s_bm[w >> 5] >> (w & 31)) & 1u;
        }
        s_c[j] = (float)cnt;
    }
    __syncthreads();

    // --- weighted gather of fv_1 rows (coalesced 512B rows, L2-resident) ---
    float acc = 0.0f;
#pragma unroll 4
    for (int j = 0; j < ns; j++) {
        acc += s_c[j] * g_fv1[s_sidx[j] * EMBED + tid];
    }
    out[v * EMBED + tid] = acc;
}

// ---------------- launch ----------------
extern "C" void kernel_launch(void* const* d_in, const int* in_sizes, int n_in,
                              void* d_out, int out_size) {
    const float* node_loc = (const float*)d_in[0];   // [4000, 2]
    const float* td       = (const float*)d_in[1];   // [4000, 1]
    const float* depot    = (const float*)d_in[2];   // [1, 2]
    const float* W0_w     = (const float*)d_in[3];   // [128, 3]
    const float* W0_b     = (const float*)d_in[4];   // [128]
    float* out = (float*)d_out;                      // [4001, 128]

    k_grid<<<1, 1024>>>(node_loc, td, depot);
    k_adj<<<(NNODES * 32 + 255) / 256, 256>>>();
    k_fv1<<<NNODES, EMBED>>>(W0_w, W0_b);
    k_fv2<<<NNODES, EMBED>>>(out);
}

// round 9
// speedup vs baseline: 3.3270x; 1.1760x over previous
#include <cuda_runtime.h>
#include <cuda_bf16.h>

// Problem constants
#define N_NODES   4000
#define NNODES    4001          // depot + nodes
#define EMBED     128
#define NC        25            // grid cells per dim (cell width = 0.04)
#define NCELLS    (NC * NC)     // 625
#define THRESH    0.04f
#define MAXS      384           // cap on 2-hop set size (expected ~80, max ~140)
#define MAXDEG    96            // cap on 1-hop degree (expected ~21, max ~50)
#define BMWORDS   128           // ceil(4001/32) = 126, padded to 128

// ---------------- device scratch (no allocations allowed) ----------------
__device__ float g_loc_x[NNODES];
__device__ float g_loc_y[NNODES];
__device__ float g_td[NNODES];
__device__ int   g_cell_start[NCELLS];
__device__ int   g_cell_count[NCELLS];
__device__ int   g_cell_nodes[NNODES];
__device__ int   g_node_cell[NNODES];
__device__ int   g_deg[NNODES];
__device__ int   g_nbr[NNODES * MAXDEG];
__device__ __align__(16) float g_fv1[NNODES * EMBED];

// ---------------- helpers ----------------
__device__ __forceinline__ int cell1d(float x) {
    int c = (int)(x * 25.0f);
    return min(NC - 1, max(0, c));
}

// Match reference: sqrt(dx*dx + dy*dy) <= 0.04f, no FMA contraction, IEEE sqrt.
__device__ __forceinline__ bool adj(float ax, float ay, float bx, float by) {
    float dx = __fadd_rn(ax, -bx);
    float dy = __fadd_rn(ay, -by);
    float d2 = __fadd_rn(__fmul_rn(dx, dx), __fmul_rn(dy, dy));
    return __fsqrt_rn(d2) <= THRESH;
}

// ---------------- fused grid build: single block, 1024 threads ----------------
__global__ void __launch_bounds__(1024) k_grid(const float* __restrict__ node_loc,
                                               const float* __restrict__ td,
                                               const float* __restrict__ depot) {
    __shared__ int s_cnt[1024];
    __shared__ int s_start[NCELLS];
    __shared__ int s_cur[NCELLS];
    __shared__ int s_scan[1024];
    int t = threadIdx.x;

    s_cnt[t] = 0;
    __syncthreads();

    // setup + count
    for (int i = t; i < NNODES; i += 1024) {
        float x, y, d;
        if (i == 0) { x = depot[0]; y = depot[1]; d = 0.0f; }
        else        { x = node_loc[(i - 1) * 2 + 0]; y = node_loc[(i - 1) * 2 + 1]; d = td[i - 1]; }
        g_loc_x[i] = x; g_loc_y[i] = y; g_td[i] = d;
        int c = cell1d(y) * NC + cell1d(x);
        g_node_cell[i] = c;
        atomicAdd(&s_cnt[c], 1);
    }
    __syncthreads();

    // inclusive scan over 625 cells -> exclusive start
    int cnt = (t < NCELLS) ? s_cnt[t] : 0;
    s_scan[t] = cnt;
    __syncthreads();
    for (int off = 1; off < 1024; off <<= 1) {
        int v = (t >= off) ? s_scan[t - off] : 0;
        __syncthreads();
        s_scan[t] += v;
        __syncthreads();
    }
    if (t < NCELLS) {
        int st = s_scan[t] - cnt;
        s_start[t] = st;
        s_cur[t]   = st;
        g_cell_start[t] = st;
        g_cell_count[t] = cnt;
    }
    __syncthreads();

    // scatter
    for (int i = t; i < NNODES; i += 1024) {
        int pos = atomicAdd(&s_cur[g_node_cell[i]], 1);
        g_cell_nodes[pos] = i;
    }
    __syncthreads();

    // deterministic order: insertion-sort each cell segment (avg ~6.4 elems)
    for (int c = t; c < NCELLS; c += 1024) {
        int s = s_start[c], n = s_scan[c] - s_start[c];
        for (int i = 1; i < n; i++) {
            int key = g_cell_nodes[s + i];
            int j = i - 1;
            while (j >= 0 && g_cell_nodes[s + j] > key) {
                g_cell_nodes[s + j + 1] = g_cell_nodes[s + j];
                j--;
            }
            g_cell_nodes[s + j + 1] = key;
        }
    }
}

// ---------------- adjacency CSR (fixed stride): one warp per vertex ----------------
__global__ void __launch_bounds__(256) k_adj() {
    int v    = (blockIdx.x * blockDim.x + threadIdx.x) >> 5;
    int lane = threadIdx.x & 31;
    if (v >= NNODES) return;

    float vx = g_loc_x[v], vy = g_loc_y[v];
    int cx = cell1d(vx), cy = cell1d(vy);
    int x0 = max(0, cx - 1), x1 = min(NC - 1, cx + 1);
    int y0 = max(0, cy - 1), y1 = min(NC - 1, cy + 1);

    int deg = 0;
    for (int yy = y0; yy <= y1; yy++) {
        int c0 = yy * NC + x0, c1 = yy * NC + x1;
        int s = g_cell_start[c0];
        int e = g_cell_start[c1] + g_cell_count[c1];
        for (int base = s; base < e; base += 32) {
            int i = base + lane;
            bool val = false;
            int u = 0;
            if (i < e) {
                u = g_cell_nodes[i];
                val = adj(vx, vy, g_loc_x[u], g_loc_y[u]);
            }
            unsigned m = __ballot_sync(0xffffffffu, val);
            int pos = deg + __popc(m & ((1u << lane) - 1u));
            if (val && pos < MAXDEG) g_nbr[v * MAXDEG + pos] = u;
            deg += __popc(m);
        }
    }
    if (lane == 0) g_deg[v] = min(deg, MAXDEG);
}

// ---------------- fv_1[v] = sum_{w in N(v)} relu(W0 * feat_w + b) ----------------
// Neighbor coords preloaded to smem in parallel -> loop is pure smem broadcasts.
__global__ void __launch_bounds__(EMBED) k_fv1(const float* __restrict__ W,
                                               const float* __restrict__ b) {
    int v = blockIdx.x;
    int d = threadIdx.x;
    __shared__ float sx[MAXDEG], sy[MAXDEG], st[MAXDEG];

    int deg = g_deg[v];
    if (d < deg) {
        int u = g_nbr[v * MAXDEG + d];
        sx[d] = g_loc_x[u];
        sy[d] = g_loc_y[u];
        st[d] = g_td[u];
    }
    __syncthreads();

    float w0 = W[d * 3 + 0], w1 = W[d * 3 + 1], w2 = W[d * 3 + 2];
    float acc = 0.0f, bb = b[d];
    for (int i = 0; i < deg; i++) {
        float f = fmaf(w2, st[i], fmaf(w1, sy[i], fmaf(w0, sx[i], bb)));
        acc += fmaxf(f, 0.0f);
    }
    g_fv1[v * EMBED + d] = acc;
}

// ---------------- fv_2[v] = sum_{u in S(v)} c_u * fv_1[u] ----------------
// S(v) marked in a 4001-bit shared bitmap, enumerated via popc+scan (ascending id).
// c_u = |N(u) ∩ S(v)| exact ints. Gather: float4, 4 rows in flight (one per warp).
__global__ void __launch_bounds__(EMBED) k_fv2(float* __restrict__ out) {
    int v    = blockIdx.x;
    int tid  = threadIdx.x;
    int lane = tid & 31;
    int warp = tid >> 5;

    __shared__ int      s_nbr[MAXDEG];
    __shared__ unsigned s_bm[BMWORDS];
    __shared__ int      s_sidx[MAXS];
    __shared__ float    s_c[MAXS];
    __shared__ int      s_wsum[4];
    __shared__ int      s_ns;
    __shared__ float4   s_acc[EMBED];

    int deg = g_deg[v];

    if (tid < deg) s_nbr[tid] = g_nbr[v * MAXDEG + tid];
    s_bm[tid] = 0u;
    __syncthreads();

    // --- mark S = union of N(w), w in N(v) (order-irrelevant bit sets) ---
    for (int i = warp; i < deg; i += 4) {
        int w  = s_nbr[i];
        int dw = g_deg[w];
        const int* nw = &g_nbr[w * MAXDEG];
        for (int k = lane; k < dw; k += 32) {
            int u = nw[k];
            atomicOr(&s_bm[u >> 5], 1u << (u & 31));
        }
    }
    __syncthreads();

    // --- enumerate S from bitmap: popc + block scan + bit extraction ---
    unsigned bw = s_bm[tid];               // words 126..127 are zero
    int cnt = __popc(bw);
    // warp-inclusive scan
    int incl = cnt;
#pragma unroll
    for (int off = 1; off < 32; off <<= 1) {
        int n = __shfl_up_sync(0xffffffffu, incl, off);
        if (lane >= off) incl += n;
    }
    if (lane == 31) s_wsum[warp] = incl;
    __syncthreads();
    int wbase = 0;
    for (int wi = 0; wi < warp; wi++) wbase += s_wsum[wi];
    int base = wbase + incl - cnt;         // exclusive prefix for this thread
    {
        int idx = tid << 5;
        unsigned w = bw;
        while (w) {
            int b = __ffs(w) - 1;
            if (base < MAXS) s_sidx[base] = idx + b;
            base++;
            w &= (w - 1);
        }
    }
    if (tid == EMBED - 1) s_ns = min(wbase + incl, MAXS);
    __syncthreads();
    int ns = s_ns;

    // --- c_u = |N(u) ∩ S| via bitmap tests ---
    for (int j = tid; j < ns; j += EMBED) {
        int u  = s_sidx[j];
        int du = g_deg[u];
        const int* nu = &g_nbr[u * MAXDEG];
        int c = 0;
        for (int k = 0; k < du; k++) {
            int w = nu[k];
            c += (s_bm[w >> 5] >> (w & 31)) & 1u;
        }
        s_c[j] = (float)c;
    }
    __syncthreads();

    // --- weighted float4 gather: warp g owns rows j ≡ g (mod 4), dims 4*lane..+3 ---
    const float4* fv1 = (const float4*)g_fv1;
    float4 acc = make_float4(0.0f, 0.0f, 0.0f, 0.0f);
    for (int j = warp; j < ns; j += 4) {
        float  c = s_c[j];
        float4 r = fv1[s_sidx[j] * 32 + lane];
        acc.x = fmaf(c, r.x, acc.x);
        acc.y = fmaf(c, r.y, acc.y);
        acc.z = fmaf(c, r.z, acc.z);
        acc.w = fmaf(c, r.w, acc.w);
    }
    s_acc[tid] = acc;
    __syncthreads();

    // reduce 4 warp-partials (fixed order -> deterministic), store 512B row
    if (warp == 0) {
        float4 a0 = s_acc[lane];
        float4 a1 = s_acc[32 + lane];
        float4 a2 = s_acc[64 + lane];
        float4 a3 = s_acc[96 + lane];
        float4 r;
        r.x = (a0.x + a1.x) + (a2.x + a3.x);
        r.y = (a0.y + a1.y) + (a2.y + a3.y);
        r.z = (a0.z + a1.z) + (a2.z + a3.z);
        r.w = (a0.w + a1.w) + (a2.w + a3.w);
        ((float4*)out)[v * 32 + lane] = r;
    }
}

// ---------------- launch ----------------
extern "C" void kernel_launch(void* const* d_in, const int* in_sizes, int n_in,
                              void* d_out, int out_size) {
    const float* node_loc = (const float*)d_in[0];   // [4000, 2]
    const float* td       = (const float*)d_in[1];   // [4000, 1]
    const float* depot    = (const float*)d_in[2];   // [1, 2]
    const float* W0_w     = (const float*)d_in[3];   // [128, 3]
    const float* W0_b     = (const float*)d_in[4];   // [128]
    float* out = (float*)d_out;                      // [4001, 128]

    k_grid<<<1, 1024>>>(node_loc, td, depot);
    k_adj<<<(NNODES * 32 + 255) / 256, 256>>>();
    k_fv1<<<NNODES, EMBED>>>(W0_w, W0_b);
    k_fv2<<<NNODES, EMBED>>>(out);
}

// round 10
// speedup vs baseline: 3.4877x; 1.0483x over previous
#include <cuda_runtime.h>
#include <cuda_bf16.h>

// Problem constants
#define N_NODES   4000
#define NNODES    4001          // depot + nodes
#define EMBED     128
#define NC        25            // grid cells per dim (cell width = 0.04)
#define NCELLS    (NC * NC)     // 625
#define THRESH    0.04f
#define MAXS      384           // cap on 2-hop set size (expected ~80, max ~140)
#define MAXDEG    96            // cap on 1-hop degree (expected ~21, max ~50)
#define BMWORDS   128           // ceil(4001/32) = 126, padded to 128
#define FV2_T     256           // 8 warps per fv2 block

// ---------------- device scratch (no allocations allowed) ----------------
__device__ float g_loc_x[NNODES];
__device__ float g_loc_y[NNODES];
__device__ float g_td[NNODES];
__device__ int   g_cell_start[NCELLS];
__device__ int   g_cell_count[NCELLS];
__device__ int   g_cell_nodes[NNODES];
__device__ int   g_node_cell[NNODES];
__device__ int   g_deg[NNODES];
__device__ int   g_nbr[NNODES * MAXDEG];
__device__ __align__(16) float g_fv1[NNODES * EMBED];

// ---------------- helpers ----------------
__device__ __forceinline__ int cell1d(float x) {
    int c = (int)(x * 25.0f);
    return min(NC - 1, max(0, c));
}

// Match reference: sqrt(dx*dx + dy*dy) <= 0.04f, no FMA contraction, IEEE sqrt.
__device__ __forceinline__ bool adj(float ax, float ay, float bx, float by) {
    float dx = __fadd_rn(ax, -bx);
    float dy = __fadd_rn(ay, -by);
    float d2 = __fadd_rn(__fmul_rn(dx, dx), __fmul_rn(dy, dy));
    return __fsqrt_rn(d2) <= THRESH;
}

// ---------------- fused grid build: single block, 1024 threads ----------------
__global__ void __launch_bounds__(1024) k_grid(const float* __restrict__ node_loc,
                                               const float* __restrict__ td,
                                               const float* __restrict__ depot) {
    __shared__ int s_cnt[1024];
    __shared__ int s_start[NCELLS];
    __shared__ int s_cur[NCELLS];
    __shared__ int s_scan[1024];
    int t = threadIdx.x;

    s_cnt[t] = 0;
    __syncthreads();

    // setup + count
    for (int i = t; i < NNODES; i += 1024) {
        float x, y, d;
        if (i == 0) { x = depot[0]; y = depot[1]; d = 0.0f; }
        else        { x = node_loc[(i - 1) * 2 + 0]; y = node_loc[(i - 1) * 2 + 1]; d = td[i - 1]; }
        g_loc_x[i] = x; g_loc_y[i] = y; g_td[i] = d;
        int c = cell1d(y) * NC + cell1d(x);
        g_node_cell[i] = c;
        atomicAdd(&s_cnt[c], 1);
    }
    __syncthreads();

    // inclusive scan over 625 cells -> exclusive start
    int cnt = (t < NCELLS) ? s_cnt[t] : 0;
    s_scan[t] = cnt;
    __syncthreads();
    for (int off = 1; off < 1024; off <<= 1) {
        int v = (t >= off) ? s_scan[t - off] : 0;
        __syncthreads();
        s_scan[t] += v;
        __syncthreads();
    }
    if (t < NCELLS) {
        int st = s_scan[t] - cnt;
        s_start[t] = st;
        s_cur[t]   = st;
        g_cell_start[t] = st;
        g_cell_count[t] = cnt;
    }
    __syncthreads();

    // scatter
    for (int i = t; i < NNODES; i += 1024) {
        int pos = atomicAdd(&s_cur[g_node_cell[i]], 1);
        g_cell_nodes[pos] = i;
    }
    __syncthreads();

    // deterministic order: insertion-sort each cell segment (avg ~6.4 elems)
    for (int c = t; c < NCELLS; c += 1024) {
        int s = s_start[c], n = s_scan[c] - s_start[c];
        for (int i = 1; i < n; i++) {
            int key = g_cell_nodes[s + i];
            int j = i - 1;
            while (j >= 0 && g_cell_nodes[s + j] > key) {
                g_cell_nodes[s + j + 1] = g_cell_nodes[s + j];
                j--;
            }
            g_cell_nodes[s + j + 1] = key;
        }
    }
}

// ---------------- fused adjacency + fv_1 : one block (128 thr) per vertex ----
// Warp 0 builds N(v) via deterministic ballot scan (coords captured in-flight),
// writes the CSR row for fv2, then all threads compute fv1 from smem.
__global__ void __launch_bounds__(EMBED) k_adj_fv1(const float* __restrict__ W,
                                                   const float* __restrict__ b) {
    int v    = blockIdx.x;
    int tid  = threadIdx.x;
    int lane = tid & 31;
    int warp = tid >> 5;

    __shared__ int   s_nbr[MAXDEG];
    __shared__ float s_nx[MAXDEG], s_ny[MAXDEG], s_nt[MAXDEG];
    __shared__ int   s_deg;

    if (warp == 0) {
        float vx = g_loc_x[v], vy = g_loc_y[v];
        int cx = cell1d(vx), cy = cell1d(vy);
        int x0 = max(0, cx - 1), x1 = min(NC - 1, cx + 1);
        int y0 = max(0, cy - 1), y1 = min(NC - 1, cy + 1);

        int deg = 0;
        for (int yy = y0; yy <= y1; yy++) {
            int c0 = yy * NC + x0, c1 = yy * NC + x1;
            int s = g_cell_start[c0];
            int e = g_cell_start[c1] + g_cell_count[c1];
            for (int base = s; base < e; base += 32) {
                int i = base + lane;
                bool val = false;
                int u = 0;
                float ux = 0.0f, uy = 0.0f;
                if (i < e) {
                    u  = g_cell_nodes[i];
                    ux = g_loc_x[u];
                    uy = g_loc_y[u];
                    val = adj(vx, vy, ux, uy);
                }
                unsigned m = __ballot_sync(0xffffffffu, val);
                int pos = deg + __popc(m & ((1u << lane) - 1u));
                if (val && pos < MAXDEG) {
                    s_nbr[pos] = u;
                    s_nx[pos]  = ux;
                    s_ny[pos]  = uy;
                    s_nt[pos]  = g_td[u];
                }
                deg += __popc(m);
            }
        }
        if (lane == 0) {
            s_deg = min(deg, MAXDEG);
            g_deg[v] = min(deg, MAXDEG);
        }
    }
    __syncthreads();
    int deg = s_deg;

    // publish CSR row for fv2 (coalesced)
    if (tid < deg) g_nbr[v * MAXDEG + tid] = s_nbr[tid];

    // fv1: thread d owns output dim d
    float w0 = W[tid * 3 + 0], w1 = W[tid * 3 + 1], w2 = W[tid * 3 + 2];
    float acc = 0.0f, bb = b[tid];
    for (int i = 0; i < deg; i++) {
        float f = fmaf(w2, s_nt[i], fmaf(w1, s_ny[i], fmaf(w0, s_nx[i], bb)));
        acc += fmaxf(f, 0.0f);
    }
    g_fv1[v * EMBED + tid] = acc;
}

// ---------------- fv_2[v] = sum_{u in S(v)} c_u * fv_1[u] ----------------
// S(v) marked in a 4001-bit shared bitmap, enumerated via popc+scan (ascending id).
// c_u = |N(u) ∩ S(v)| computed warp-cooperatively with COALESCED N(u) reads.
// Gather: float4, 8 rows in flight (one per warp), fixed-order 8-way reduce.
__global__ void __launch_bounds__(FV2_T) k_fv2(float* __restrict__ out) {
    int v    = blockIdx.x;
    int tid  = threadIdx.x;
    int lane = tid & 31;
    int warp = tid >> 5;

    __shared__ unsigned s_bm[BMWORDS];
    __shared__ int      s_sidx[MAXS];
    __shared__ float    s_c[MAXS];
    __shared__ int      s_wsum[FV2_T / 32];
    __shared__ int      s_ns;
    __shared__ float4   s_acc[FV2_T];

    int deg = g_deg[v];

    if (tid < BMWORDS) s_bm[tid] = 0u;
    __syncthreads();

    // --- Phase A: mark S = union of N(w), w in N(v). Coalesced row reads. ---
    for (int i = warp; i < deg; i += FV2_T / 32) {
        int w  = g_nbr[v * MAXDEG + i];       // broadcast (all lanes same addr)
        int dw = g_deg[w];                    // broadcast
        const int* nw = &g_nbr[w * MAXDEG];
        for (int k = lane; k < dw; k += 32) { // coalesced
            int u = nw[k];
            atomicOr(&s_bm[u >> 5], 1u << (u & 31));
        }
    }
    __syncthreads();

    // --- Phase B: enumerate S from bitmap (popc + block scan + bit extract) ---
    unsigned bw = (tid < BMWORDS) ? s_bm[tid] : 0u;
    int cnt = __popc(bw);
    int incl = cnt;
#pragma unroll
    for (int off = 1; off < 32; off <<= 1) {
        int n = __shfl_up_sync(0xffffffffu, incl, off);
        if (lane >= off) incl += n;
    }
    if (lane == 31) s_wsum[warp] = incl;
    __syncthreads();
    int wbase = 0;
#pragma unroll
    for (int wi = 0; wi < FV2_T / 32; wi++) wbase += (wi < warp) ? s_wsum[wi] : 0;
    int base = wbase + incl - cnt;            // exclusive prefix for this thread
    {
        int idx = tid << 5;
        unsigned w = bw;
        while (w) {
            int bpos = __ffs(w) - 1;
            if (base < MAXS) s_sidx[base] = idx + bpos;
            base++;
            w &= (w - 1);
        }
    }
    if (tid == FV2_T - 1) {
        int total = wbase + incl;
        s_ns = min(total, MAXS);
    }
    __syncthreads();
    int ns = s_ns;

    // --- Phase C: c_u = |N(u) ∩ S| — warp per u, coalesced N(u) read + ballot ---
    for (int j = warp; j < ns; j += FV2_T / 32) {
        int u  = s_sidx[j];
        int du = g_deg[u];                    // broadcast
        const int* nu = &g_nbr[u * MAXDEG];
        int c = 0;
        for (int kb = 0; kb < du; kb += 32) {
            int k = kb + lane;
            bool hit = false;
            if (k < du) {
                int w = nu[k];                // coalesced
                hit = (s_bm[w >> 5] >> (w & 31)) & 1u;
            }
            c += __popc(__ballot_sync(0xffffffffu, hit));
        }
        if (lane == 0) s_c[j] = (float)c;
    }
    __syncthreads();

    // --- Phase D: weighted float4 gather, 8 rows in flight ---
    const float4* fv1 = (const float4*)g_fv1;
    float4 acc = make_float4(0.0f, 0.0f, 0.0f, 0.0f);
    for (int j = warp; j < ns; j += FV2_T / 32) {
        float  c = s_c[j];
        float4 r = fv1[s_sidx[j] * 32 + lane];
        acc.x = fmaf(c, r.x, acc.x);
        acc.y = fmaf(c, r.y, acc.y);
        acc.z = fmaf(c, r.z, acc.z);
        acc.w = fmaf(c, r.w, acc.w);
    }
    s_acc[tid] = acc;
    __syncthreads();

    // fixed-order 8-way reduce (deterministic), one 512B row store
    if (warp == 0) {
        float4 a0 = s_acc[lane];
        float4 a1 = s_acc[32 + lane];
        float4 a2 = s_acc[64 + lane];
        float4 a3 = s_acc[96 + lane];
        float4 a4 = s_acc[128 + lane];
        float4 a5 = s_acc[160 + lane];
        float4 a6 = s_acc[192 + lane];
        float4 a7 = s_acc[224 + lane];
        float4 r;
        r.x = ((a0.x + a1.x) + (a2.x + a3.x)) + ((a4.x + a5.x) + (a6.x + a7.x));
        r.y = ((a0.y + a1.y) + (a2.y + a3.y)) + ((a4.y + a5.y) + (a6.y + a7.y));
        r.z = ((a0.z + a1.z) + (a2.z + a3.z)) + ((a4.z + a5.z) + (a6.z + a7.z));
        r.w = ((a0.w + a1.w) + (a2.w + a3.w)) + ((a4.w + a5.w) + (a6.w + a7.w));
        ((float4*)out)[v * 32 + lane] = r;
    }
}

// ---------------- launch ----------------
extern "C" void kernel_launch(void* const* d_in, const int* in_sizes, int n_in,
                              void* d_out, int out_size) {
    const float* node_loc = (const float*)d_in[0];   // [4000, 2]
    const float* td       = (const float*)d_in[1];   // [4000, 1]
    const float* depot    = (const float*)d_in[2];   // [1, 2]
    const float* W0_w     = (const float*)d_in[3];   // [128, 3]
    const float* W0_b     = (const float*)d_in[4];   // [128]
    float* out = (float*)d_out;                      // [4001, 128]

    k_grid<<<1, 1024>>>(node_loc, td, depot);
    k_adj_fv1<<<NNODES, EMBED>>>(W0_w, W0_b);
    k_fv2<<<NNODES, FV2_T>>>(out);
}